// round 12
// baseline (speedup 1.0000x reference)
#include <cuda_runtime.h>
#include <math.h>
#include <stdint.h>

#define BB 8
#define SS 2048
#define DD 768
#define BS (BB * SS)

// Scratch (no cudaMalloc allowed)
__device__ float g_Zr[BS * DD];                 // tf32-rounded Z
__device__ float g_Wr[3 * DD * DD];             // tf32-rounded Wq,Wk,Wv (contig)
__device__ float g_bqk[2 * DD];                 // concat bias [bq | bk]
__device__ float g_QK[(long long)BS * 2 * DD];  // [bs][1536]: Q cols 0..767, K cols 768..1535
__device__ float g_Vt[BS * DD];                 // layout [e][b*s] (ld = BS)
__device__ float g_P[(long long)BB * SS * SS];

// Smem: 2-stage pipeline, A tile 256x16, B tile 128x16, padded [row][20]
#define STAGE_A (256 * 20 * 4)
#define STAGE_B (128 * 20 * 4)
#define SMEM_BYTES (2 * STAGE_A + 2 * STAGE_B)

// cvt.rna.tf32.f32 requires a .b32 destination register
__device__ __forceinline__ float tf32r(float x) {
    uint32_t y;
    asm("cvt.rna.tf32.f32 %0, %1;" : "=r"(y) : "f"(x));
    return __uint_as_float(y);
}
__device__ __forceinline__ uint32_t tf32u(uint32_t x) {
    uint32_t y;
    asm("cvt.rna.tf32.f32 %0, %1;" : "=r"(y) : "f"(__uint_as_float(x)));
    return y;
}

__device__ __forceinline__ void mma_tf32(float c[4],
                                         uint32_t a0, uint32_t a1, uint32_t a2, uint32_t a3,
                                         uint32_t b0, uint32_t b1) {
    asm volatile(
        "mma.sync.aligned.m16n8k8.row.col.f32.tf32.tf32.f32 "
        "{%0,%1,%2,%3}, {%4,%5,%6,%7}, {%8,%9}, {%0,%1,%2,%3};\n"
        : "+f"(c[0]), "+f"(c[1]), "+f"(c[2]), "+f"(c[3])
        : "r"(a0), "r"(a1), "r"(a2), "r"(a3), "r"(b0), "r"(b1));
}

// ldmatrix x4 of 8x8 b16 matrices == four 8x4 tf32 blocks; thread t receives
// tf32 element (t/4, t%4) of each matrix -> exact tf32 mma fragment layout.
__device__ __forceinline__ void ldsm4(uint32_t& r0, uint32_t& r1, uint32_t& r2, uint32_t& r3,
                                      uint32_t addr) {
    asm volatile("ldmatrix.sync.aligned.m8n8.x4.shared.b16 {%0,%1,%2,%3}, [%4];\n"
                 : "=r"(r0), "=r"(r1), "=r"(r2), "=r"(r3) : "r"(addr));
}

__device__ __forceinline__ void cpasync16(uint32_t dst, const void* src) {
    asm volatile("cp.async.cg.shared.global [%0], [%1], 16;\n" :: "r"(dst), "l"(src));
}

// ---------------------------------------------------------------------------
// tf32 tensor-core NT GEMM: C = scale*(A @ B^T) + bias
//   A:[M,K] ld=lda, B:[N,K] ld=ldb (both K-contiguous), C:[M,N] ld=ldc.
// CTA tile 256(M)x128(N), Kc=16, 2-stage cp.async pipeline, 256 threads,
// warp grid 4(M)x2(N): warp tile 64x64 = 4x8 m16n8k8 mma tiles.
// Per K=8: 8 ldmatrix.x4 feed 32 mmas (vs 6:16 at 32x64) -> less smem pressure.
// CVT: round operands to tf32 at consume. RND: round outputs to tf32.
// BROW: bias indexed by M-row (transposed-V projection) else by N-col.
// ---------------------------------------------------------------------------
template <bool CVT, bool RND, bool BROW>
__global__ void __launch_bounds__(256, 1)
gemm_nt(const float* __restrict__ A, const float* __restrict__ Bm,
        const float* __restrict__ bias, float* __restrict__ C,
        int K, int lda, int ldb, int ldc,
        long long sA, long long sB, long long sC, float scale)
{
    extern __shared__ __align__(16) float smem[];

    const int b = blockIdx.z;
    A  += (long long)b * sA;
    Bm += (long long)b * sB;
    C  += (long long)b * sC;

    const int tid   = threadIdx.x;
    const int lane  = tid & 31;
    const int warp  = tid >> 5;
    const int warpM = warp & 3;       // 0..3 -> 64-row slab
    const int warpN = warp >> 2;      // 0..1 -> 64-col slab
    const int grp   = lane >> 2;      // 0..7
    const int qid   = lane & 3;       // 0..3
    const int m0    = blockIdx.y * 256;
    const int n0    = blockIdx.x * 128;

    // ldmatrix per-thread row assignment: local row + matrix select
    const int local = lane & 7;
    const int sel   = lane >> 3;      // 0..3
    // A: matrices (row-lo,k-lo),(row-hi,k-lo),(row-lo,k-hi),(row-hi,k-hi)
    const int rowA = warpM * 64 + ((sel & 1) << 3) + local;
    const int kcA  = (sel >> 1) << 2;
    // B: matrices (n-lo,k-lo),(n-lo,k-hi),(n-hi,k-lo),(n-hi,k-hi)
    const int rowB = warpN * 64 + ((sel >> 1) << 3) + local;
    const int kcB  = (sel & 1) << 2;

    const uint32_t as_base = (uint32_t)__cvta_generic_to_shared(smem);
    const uint32_t bs_base = as_base + 2 * STAGE_A;

    float acc[4][8][4];
#pragma unroll
    for (int mt = 0; mt < 4; mt++)
#pragma unroll
        for (int nt = 0; nt < 8; nt++)
#pragma unroll
            for (int r = 0; r < 4; r++) acc[mt][nt][r] = 0.f;

    // ---- async stage loader: A 256x16, B 128x16 (both K-contiguous)
    auto load_stage = [&](int k0, int s) {
#pragma unroll
        for (int i = 0; i < 4; i++) {
            int slot = tid + i * 256;            // 0..1023
            int row  = slot >> 2;                // 0..255
            int c4   = (slot & 3) << 2;          // 0,4,8,12
            cpasync16(as_base + s * STAGE_A + (row * 20 + c4) * 4,
                      &A[(long long)(m0 + row) * lda + k0 + c4]);
        }
#pragma unroll
        for (int i = 0; i < 2; i++) {
            int slot = tid + i * 256;            // 0..511
            int row  = slot >> 2;                // 0..127
            int c4   = (slot & 3) << 2;
            cpasync16(bs_base + s * STAGE_B + (row * 20 + c4) * 4,
                      &Bm[(long long)(n0 + row) * ldb + k0 + c4]);
        }
        asm volatile("cp.async.commit_group;\n" ::);
    };

    const int NK = K >> 4;
    load_stage(0, 0);

    for (int it = 0; it < NK; it++) {
        if (it + 1 < NK) {
            load_stage((it + 1) << 4, (it + 1) & 1);
            asm volatile("cp.async.wait_group 1;\n" ::);
        } else {
            asm volatile("cp.async.wait_group 0;\n" ::);
        }
        __syncthreads();

        const uint32_t as_s = as_base + (it & 1) * STAGE_A;
        const uint32_t bs_s = bs_base + (it & 1) * STAGE_B;

#pragma unroll
        for (int ks = 0; ks < 2; ks++) {
            const int kb = ks * 8;
            uint32_t af[4][4];
#pragma unroll
            for (int mt = 0; mt < 4; mt++) {
                uint32_t addr = as_s + (((rowA + mt * 16) * 20) + kb + kcA) * 4;
                ldsm4(af[mt][0], af[mt][1], af[mt][2], af[mt][3], addr);
                if (CVT) {
                    af[mt][0] = tf32u(af[mt][0]); af[mt][1] = tf32u(af[mt][1]);
                    af[mt][2] = tf32u(af[mt][2]); af[mt][3] = tf32u(af[mt][3]);
                }
            }
#pragma unroll
            for (int p = 0; p < 4; p++) {       // nt pair p -> nt=2p, 2p+1
                uint32_t b0, b1, b2, b3;
                uint32_t addr = bs_s + (((rowB + p * 16) * 20) + kb + kcB) * 4;
                ldsm4(b0, b1, b2, b3, addr);
                if (CVT) { b0 = tf32u(b0); b1 = tf32u(b1); b2 = tf32u(b2); b3 = tf32u(b3); }
#pragma unroll
                for (int mt = 0; mt < 4; mt++) {
                    mma_tf32(acc[mt][2 * p],     af[mt][0], af[mt][1], af[mt][2], af[mt][3], b0, b1);
                    mma_tf32(acc[mt][2 * p + 1], af[mt][0], af[mt][1], af[mt][2], af[mt][3], b2, b3);
                }
            }
        }
        __syncthreads();
    }

    // ---- epilogue: scale + bias (+ optional tf32 rounding), float2 stores
#pragma unroll
    for (int nt = 0; nt < 8; nt++) {
        int colc = n0 + warpN * 64 + nt * 8 + (qid << 1);
        float bc0 = 0.f, bc1 = 0.f;
        if (bias && !BROW) { bc0 = bias[colc]; bc1 = bias[colc + 1]; }
#pragma unroll
        for (int mt = 0; mt < 4; mt++) {
            int row0 = m0 + warpM * 64 + mt * 16 + grp;
            float br0 = 0.f, br1 = 0.f;
            if (bias && BROW) { br0 = bias[row0]; br1 = bias[row0 + 8]; }
            float2 o0, o1;
            o0.x = acc[mt][nt][0] * scale + (BROW ? br0 : bc0);
            o0.y = acc[mt][nt][1] * scale + (BROW ? br0 : bc1);
            o1.x = acc[mt][nt][2] * scale + (BROW ? br1 : bc0);
            o1.y = acc[mt][nt][3] * scale + (BROW ? br1 : bc1);
            if (RND) {
                o0.x = tf32r(o0.x); o0.y = tf32r(o0.y);
                o1.x = tf32r(o1.x); o1.y = tf32r(o1.y);
            }
            *(float2*)&C[(long long)row0 * ldc + colc]       = o0;
            *(float2*)&C[(long long)(row0 + 8) * ldc + colc] = o1;
        }
    }
}

// ---------------------------------------------------------------------------
// Elementwise tf32 (rna) rounding: out[i] = round_tf32(in[i]), float4 strided.
// ---------------------------------------------------------------------------
__global__ void __launch_bounds__(256)
round_tf32_k(const float* __restrict__ in, float* __restrict__ out, int n4)
{
    int i = blockIdx.x * blockDim.x + threadIdx.x;
    if (i < n4) {
        float4 v = ((const float4*)in)[i];
        v.x = tf32r(v.x); v.y = tf32r(v.y); v.z = tf32r(v.z); v.w = tf32r(v.w);
        ((float4*)out)[i] = v;
    }
}

// Concatenate bq|bk into one 1536-entry bias vector
__global__ void __launch_bounds__(256)
concat_bias_k(const float* __restrict__ bq, const float* __restrict__ bk,
              float* __restrict__ outb)
{
    int i = blockIdx.x * blockDim.x + threadIdx.x;
    if (i < DD)           outb[i] = bq[i];
    else if (i < 2 * DD)  outb[i] = bk[i - DD];
}

// ---------------------------------------------------------------------------
// Row softmax over P rows of length SS (2048). One block (256 thr) per row.
// Output rounded to tf32 (PV consumes pre-rounded operands).
// ---------------------------------------------------------------------------
__global__ void __launch_bounds__(256)
softmax_rows(float* __restrict__ P)
{
    float* p = P + (long long)blockIdx.x * SS;
    const int tid  = threadIdx.x;
    const int lane = tid & 31;
    const int wid  = tid >> 5;

    __shared__ float red[8];

    float v[8];
    float mx = -1e30f;
#pragma unroll
    for (int i = 0; i < 8; i++) {
        v[i] = p[tid + i * 256];
        mx = fmaxf(mx, v[i]);
    }
#pragma unroll
    for (int o = 16; o > 0; o >>= 1)
        mx = fmaxf(mx, __shfl_xor_sync(0xffffffffu, mx, o));
    if (lane == 0) red[wid] = mx;
    __syncthreads();
    float rmax = red[0];
#pragma unroll
    for (int i = 1; i < 8; i++) rmax = fmaxf(rmax, red[i]);
    __syncthreads();

    float s = 0.f;
#pragma unroll
    for (int i = 0; i < 8; i++) {
        v[i] = __expf(v[i] - rmax);
        s += v[i];
    }
#pragma unroll
    for (int o = 16; o > 0; o >>= 1)
        s += __shfl_xor_sync(0xffffffffu, s, o);
    if (lane == 0) red[wid] = s;
    __syncthreads();
    float tot = 0.f;
#pragma unroll
    for (int i = 0; i < 8; i++) tot += red[i];
    float inv = 1.f / tot;

#pragma unroll
    for (int i = 0; i < 8; i++)
        p[tid + i * 256] = tf32r(v[i] * inv);
}

// ---------------------------------------------------------------------------
// Launch: round inputs -> merged QK proj + Vt proj -> scores -> softmax -> PV
// ---------------------------------------------------------------------------
extern "C" void kernel_launch(void* const* d_in, const int* in_sizes, int n_in,
                              void* d_out, int out_size)
{
    const float* Z  = (const float*)d_in[0];
    const float* Wq = (const float*)d_in[1];
    const float* bq = (const float*)d_in[2];
    const float* Wk = (const float*)d_in[3];
    const float* bk = (const float*)d_in[4];
    const float* Wv = (const float*)d_in[5];
    const float* bv = (const float*)d_in[6];
    float* out = (float*)d_out;

    float *Zr, *Wr, *bqk, *QKp, *Vtp, *Pp;
    cudaGetSymbolAddress((void**)&Zr,  g_Zr);
    cudaGetSymbolAddress((void**)&Wr,  g_Wr);
    cudaGetSymbolAddress((void**)&bqk, g_bqk);
    cudaGetSymbolAddress((void**)&QKp, g_QK);
    cudaGetSymbolAddress((void**)&Vtp, g_Vt);
    cudaGetSymbolAddress((void**)&Pp,  g_P);

    cudaFuncSetAttribute(gemm_nt<true,  true,  false>,
                         cudaFuncAttributeMaxDynamicSharedMemorySize, SMEM_BYTES);
    cudaFuncSetAttribute(gemm_nt<true,  true,  true>,
                         cudaFuncAttributeMaxDynamicSharedMemorySize, SMEM_BYTES);
    cudaFuncSetAttribute(gemm_nt<false, false, false>,
                         cudaFuncAttributeMaxDynamicSharedMemorySize, SMEM_BYTES);

    dim3 blk(256);
    const long long SD   = (long long)SS * DD;
    const long long SQK  = (long long)SS * 2 * DD;
    const long long SSs  = (long long)SS * SS;
    const float scale = 1.0f / sqrtf((float)DD);

    // Pre-round inputs to tf32 (rna); Wq,Wk,Wv land contiguous in g_Wr
    const int nZ4 = (BS * DD) / 4, nW4 = (DD * DD) / 4;
    round_tf32_k<<<(nZ4 + 255) / 256, blk>>>(Z,  Zr, nZ4);
    round_tf32_k<<<(nW4 + 255) / 256, blk>>>(Wq, Wr + 0 * DD * DD, nW4);
    round_tf32_k<<<(nW4 + 255) / 256, blk>>>(Wk, Wr + 1 * DD * DD, nW4);
    round_tf32_k<<<(nW4 + 255) / 256, blk>>>(Wv, Wr + 2 * DD * DD, nW4);
    concat_bias_k<<<(2 * DD + 255) / 256, blk>>>(bq, bk, bqk);

    // Merged Q|K projection: [BS,768] x [1536,768]^T -> g_QK [BS][1536]
    dim3 gqk((2 * DD) / 128, BS / 256, 1);
    gemm_nt<true, true, false><<<gqk, blk, SMEM_BYTES>>>(
        Zr, Wr, bqk, QKp, DD, DD, DD, 2 * DD, 0, 0, 0, 1.0f);

    // Transposed V projection: Vt = Wv @ Z^T (M=768, N=BS, K=768), bias per M-row
    dim3 gv(BS / 128, DD / 256, 1);
    gemm_nt<true, true, true ><<<gv, blk, SMEM_BYTES>>>(
        Wr + 2 * DD * DD, Zr, bv, Vtp, DD, DD, DD, BS, 0, 0, 0, 1.0f);

    // Scores: per batch, Q @ K^T * scale (M=N=2048, K=768)
    // Q = g_QK cols 0..767 (lda=1536), K = g_QK cols 768..1535 (ldb=1536)
    dim3 gs(SS / 128, SS / 256, BB);
    gemm_nt<false, false, false><<<gs, blk, SMEM_BYTES>>>(
        QKp, QKp + DD, nullptr, Pp, DD, 2 * DD, 2 * DD, SS, SQK, SQK, SSs, scale);

    // Softmax over each of BS rows (rounds P to tf32 on store)
    softmax_rows<<<BS, blk>>>(Pp);

    // Output: per batch, P @ Vt^T (M=2048, N=768, K=2048); B=Vt ld=BS, stride SS
    dim3 go(DD / 128, SS / 256, BB);
    gemm_nt<false, false, false><<<go, blk, SMEM_BYTES>>>(
        Pp, Vtp, nullptr, out, SS, SS, BS, DD, SSs, SS, SD, 1.0f);
}

// round 15
// speedup vs baseline: 1.1807x; 1.1807x over previous
#include <cuda_runtime.h>
#include <math.h>
#include <stdint.h>

#define BB 8
#define SS 2048
#define DD 768
#define BS (BB * SS)

// Scratch (no cudaMalloc allowed): Q,K projections, transposed V, score matrix
__device__ float g_Q[BS * DD];
__device__ float g_K[BS * DD];
__device__ float g_Vt[BS * DD];   // layout [e][b*s]  (ld = BS)
__device__ float g_P[(long long)BB * SS * SS];

// 2-stage pipeline, tiles [128][36] (Kc=32 + 4 pad): conflict-free for ldmatrix
#define STAGE_B4 (128 * 36 * 4)
#define SMEM_BYTES (4 * STAGE_B4)   // A0,A1,B0,B1 = 72KB

// cvt.rna.tf32.f32 requires a .b32 destination register
__device__ __forceinline__ float tf32r(float x) {
    uint32_t y;
    asm("cvt.rna.tf32.f32 %0, %1;" : "=r"(y) : "f"(x));
    return __uint_as_float(y);
}
__device__ __forceinline__ uint32_t tf32u(uint32_t x) {
    uint32_t y;
    asm("cvt.rna.tf32.f32 %0, %1;" : "=r"(y) : "f"(__uint_as_float(x)));
    return y;
}

__device__ __forceinline__ void mma_tf32(float c[4],
                                         uint32_t a0, uint32_t a1, uint32_t a2, uint32_t a3,
                                         uint32_t b0, uint32_t b1) {
    asm volatile(
        "mma.sync.aligned.m16n8k8.row.col.f32.tf32.tf32.f32 "
        "{%0,%1,%2,%3}, {%4,%5,%6,%7}, {%8,%9}, {%0,%1,%2,%3};\n"
        : "+f"(c[0]), "+f"(c[1]), "+f"(c[2]), "+f"(c[3])
        : "r"(a0), "r"(a1), "r"(a2), "r"(a3), "r"(b0), "r"(b1));
}

// ldmatrix x4 of 8x8 b16 matrices == four 8x4 tf32 blocks; thread t receives
// tf32 element (t/4, t%4) of each matrix -> exact tf32 mma fragment layout.
__device__ __forceinline__ void ldsm4(uint32_t& r0, uint32_t& r1, uint32_t& r2, uint32_t& r3,
                                      uint32_t addr) {
    asm volatile("ldmatrix.sync.aligned.m8n8.x4.shared.b16 {%0,%1,%2,%3}, [%4];\n"
                 : "=r"(r0), "=r"(r1), "=r"(r2), "=r"(r3) : "r"(addr));
}

__device__ __forceinline__ void cpasync16(uint32_t dst, const void* src) {
    asm volatile("cp.async.cg.shared.global [%0], [%1], 16;\n" :: "r"(dst), "l"(src));
}

// ---------------------------------------------------------------------------
// tf32 tensor-core NT GEMM: C = scale*(A @ B^T) + bias
//   A:[M,K] ld=lda, B:[N,K] ld=ldb (both K-contiguous), C:[M,N] ld=ldc.
// 128x128 block tile, Kc=32 (4 K=8 slabs per barrier), 2-stage cp.async
// pipeline, 256 threads (8 warps), warp tile 32(M)x64(N) = 2x8 mma tiles.
// B-fragments double-buffered across slabs: slab ks+1's 4 B-ldsm issue while
// slab ks's 16 mmas run -> hides 2/3 of LDSM latency, kills convoy stalls.
// CVT: round operands to tf32 at consume. RND: round outputs to tf32.
// BROW: bias indexed by M-row (transposed-V projection) else by N-col.
// Smem [128][36]: bank=(4r+c)%32 -> ldmatrix 8 rows x 4 words = all 32 banks.
// ---------------------------------------------------------------------------
template <bool CVT, bool RND, bool BROW>
__global__ void __launch_bounds__(256, 2)
gemm_nt(const float* __restrict__ A, const float* __restrict__ Bm,
        const float* __restrict__ bias, float* __restrict__ C,
        int K, int lda, int ldb, int ldc,
        long long sA, long long sB, long long sC, float scale)
{
    extern __shared__ __align__(16) float smem[];

    const int b = blockIdx.z;
    A  += (long long)b * sA;
    Bm += (long long)b * sB;
    C  += (long long)b * sC;

    const int tid   = threadIdx.x;
    const int lane  = tid & 31;
    const int warp  = tid >> 5;
    const int warpM = warp & 3;       // 0..3 -> 32-row slab
    const int warpN = warp >> 2;      // 0..1 -> 64-col slab
    const int grp   = lane >> 2;      // 0..7
    const int qid   = lane & 3;       // 0..3
    const int m0    = blockIdx.y * 128;
    const int n0    = blockIdx.x * 128;

    // ldmatrix per-thread row assignment: local row + matrix select
    const int local = lane & 7;
    const int sel   = lane >> 3;      // 0..3
    // A: matrices (row-lo,k-lo),(row-hi,k-lo),(row-lo,k-hi),(row-hi,k-hi)
    const int rowA = warpM * 32 + ((sel & 1) << 3) + local;
    const int kcA  = (sel >> 1) << 2;
    // B: matrices (n-lo,k-lo),(n-lo,k-hi),(n-hi,k-lo),(n-hi,k-hi)
    const int rowB = warpN * 64 + ((sel >> 1) << 3) + local;
    const int kcB  = (sel & 1) << 2;

    const uint32_t as_base = (uint32_t)__cvta_generic_to_shared(smem);
    const uint32_t bs_base = as_base + 2 * STAGE_B4;

    float acc[2][8][4];
#pragma unroll
    for (int mt = 0; mt < 2; mt++)
#pragma unroll
        for (int nt = 0; nt < 8; nt++)
#pragma unroll
            for (int r = 0; r < 4; r++) acc[mt][nt][r] = 0.f;

    // ---- async stage loader: A 128x32, B 128x32 (both K-contiguous)
    auto load_stage = [&](int k0, int s) {
#pragma unroll
        for (int i = 0; i < 4; i++) {
            int slot = tid + i * 256;            // 0..1023
            int row  = slot >> 3;                // 0..127
            int c4   = (slot & 7) << 2;          // 0,4,...,28
            cpasync16(as_base + s * STAGE_B4 + (row * 36 + c4) * 4,
                      &A[(long long)(m0 + row) * lda + k0 + c4]);
            cpasync16(bs_base + s * STAGE_B4 + (row * 36 + c4) * 4,
                      &Bm[(long long)(n0 + row) * ldb + k0 + c4]);
        }
        asm volatile("cp.async.commit_group;\n" ::);
    };

    const int NK = K >> 5;            // K / 32
    load_stage(0, 0);

    for (int it = 0; it < NK; it++) {
        if (it + 1 < NK) {
            load_stage((it + 1) << 5, (it + 1) & 1);
            asm volatile("cp.async.wait_group 1;\n" ::);
        } else {
            asm volatile("cp.async.wait_group 0;\n" ::);
        }
        __syncthreads();

        const uint32_t as_s = as_base + (it & 1) * STAGE_B4;
        const uint32_t bs_s = bs_base + (it & 1) * STAGE_B4;

        // B-fragment double buffer: preload slab 0
        uint32_t bf[2][4][4];
#pragma unroll
        for (int p = 0; p < 4; p++) {
            uint32_t addr = bs_s + (((rowB + p * 16) * 36) + kcB) * 4;
            ldsm4(bf[0][p][0], bf[0][p][1], bf[0][p][2], bf[0][p][3], addr);
            if (CVT) {
                bf[0][p][0] = tf32u(bf[0][p][0]); bf[0][p][1] = tf32u(bf[0][p][1]);
                bf[0][p][2] = tf32u(bf[0][p][2]); bf[0][p][3] = tf32u(bf[0][p][3]);
            }
        }

#pragma unroll
        for (int ks = 0; ks < 4; ks++) {
            const int cur = ks & 1, nxt = cur ^ 1;
            const int kb  = ks * 8;

            // A fragments for this slab
            uint32_t af[2][4];
#pragma unroll
            for (int mt = 0; mt < 2; mt++) {
                uint32_t addr = as_s + (((rowA + mt * 16) * 36) + kb + kcA) * 4;
                ldsm4(af[mt][0], af[mt][1], af[mt][2], af[mt][3], addr);
                if (CVT) {
                    af[mt][0] = tf32u(af[mt][0]); af[mt][1] = tf32u(af[mt][1]);
                    af[mt][2] = tf32u(af[mt][2]); af[mt][3] = tf32u(af[mt][3]);
                }
            }
            // Prefetch next slab's B fragments (hidden under this slab's mmas)
            if (ks < 3) {
#pragma unroll
                for (int p = 0; p < 4; p++) {
                    uint32_t addr = bs_s + (((rowB + p * 16) * 36) + kb + 8 + kcB) * 4;
                    ldsm4(bf[nxt][p][0], bf[nxt][p][1], bf[nxt][p][2], bf[nxt][p][3], addr);
                    if (CVT) {
                        bf[nxt][p][0] = tf32u(bf[nxt][p][0]); bf[nxt][p][1] = tf32u(bf[nxt][p][1]);
                        bf[nxt][p][2] = tf32u(bf[nxt][p][2]); bf[nxt][p][3] = tf32u(bf[nxt][p][3]);
                    }
                }
            }
#pragma unroll
            for (int p = 0; p < 4; p++) {
#pragma unroll
                for (int mt = 0; mt < 2; mt++) {
                    mma_tf32(acc[mt][2 * p],     af[mt][0], af[mt][1], af[mt][2], af[mt][3],
                             bf[cur][p][0], bf[cur][p][1]);
                    mma_tf32(acc[mt][2 * p + 1], af[mt][0], af[mt][1], af[mt][2], af[mt][3],
                             bf[cur][p][2], bf[cur][p][3]);
                }
            }
        }
        __syncthreads();
    }

    // ---- epilogue: scale + bias (+ optional tf32 rounding), float2 stores
#pragma unroll
    for (int nt = 0; nt < 8; nt++) {
        int colc = n0 + warpN * 64 + nt * 8 + (qid << 1);
        float bc0 = 0.f, bc1 = 0.f;
        if (bias && !BROW) { bc0 = bias[colc]; bc1 = bias[colc + 1]; }
#pragma unroll
        for (int mt = 0; mt < 2; mt++) {
            int row0 = m0 + warpM * 32 + mt * 16 + grp;
            float br0 = 0.f, br1 = 0.f;
            if (bias && BROW) { br0 = bias[row0]; br1 = bias[row0 + 8]; }
            float2 o0, o1;
            o0.x = acc[mt][nt][0] * scale + (BROW ? br0 : bc0);
            o0.y = acc[mt][nt][1] * scale + (BROW ? br0 : bc1);
            o1.x = acc[mt][nt][2] * scale + (BROW ? br1 : bc0);
            o1.y = acc[mt][nt][3] * scale + (BROW ? br1 : bc1);
            if (RND) {
                o0.x = tf32r(o0.x); o0.y = tf32r(o0.y);
                o1.x = tf32r(o1.x); o1.y = tf32r(o1.y);
            }
            *(float2*)&C[(long long)row0 * ldc + colc]       = o0;
            *(float2*)&C[(long long)(row0 + 8) * ldc + colc] = o1;
        }
    }
}

// ---------------------------------------------------------------------------
// Row softmax over P rows of length SS (2048). One block (256 thr) per row.
// Output rounded to tf32 so the PV GEMM can skip per-element cvt.
// ---------------------------------------------------------------------------
__global__ void __launch_bounds__(256)
softmax_rows(float* __restrict__ P)
{
    float* p = P + (long long)blockIdx.x * SS;
    const int tid  = threadIdx.x;
    const int lane = tid & 31;
    const int wid  = tid >> 5;

    __shared__ float red[8];

    float v[8];
    float mx = -1e30f;
#pragma unroll
    for (int i = 0; i < 8; i++) {
        v[i] = p[tid + i * 256];
        mx = fmaxf(mx, v[i]);
    }
#pragma unroll
    for (int o = 16; o > 0; o >>= 1)
        mx = fmaxf(mx, __shfl_xor_sync(0xffffffffu, mx, o));
    if (lane == 0) red[wid] = mx;
    __syncthreads();
    float rmax = red[0];
#pragma unroll
    for (int i = 1; i < 8; i++) rmax = fmaxf(rmax, red[i]);
    __syncthreads();

    float s = 0.f;
#pragma unroll
    for (int i = 0; i < 8; i++) {
        v[i] = __expf(v[i] - rmax);
        s += v[i];
    }
#pragma unroll
    for (int o = 16; o > 0; o >>= 1)
        s += __shfl_xor_sync(0xffffffffu, s, o);
    if (lane == 0) red[wid] = s;
    __syncthreads();
    float tot = 0.f;
#pragma unroll
    for (int i = 0; i < 8; i++) tot += red[i];
    float inv = 1.f / tot;

#pragma unroll
    for (int i = 0; i < 8; i++)
        p[tid + i * 256] = tf32r(v[i] * inv);
}

// ---------------------------------------------------------------------------
// Launch: Q,K projections + transposed V projection -> scores -> softmax -> PV
// ---------------------------------------------------------------------------
extern "C" void kernel_launch(void* const* d_in, const int* in_sizes, int n_in,
                              void* d_out, int out_size)
{
    const float* Z  = (const float*)d_in[0];
    const float* Wq = (const float*)d_in[1];
    const float* bq = (const float*)d_in[2];
    const float* Wk = (const float*)d_in[3];
    const float* bk = (const float*)d_in[4];
    const float* Wv = (const float*)d_in[5];
    const float* bv = (const float*)d_in[6];
    float* out = (float*)d_out;

    float *Qp, *Kp, *Vtp, *Pp;
    cudaGetSymbolAddress((void**)&Qp,  g_Q);
    cudaGetSymbolAddress((void**)&Kp,  g_K);
    cudaGetSymbolAddress((void**)&Vtp, g_Vt);
    cudaGetSymbolAddress((void**)&Pp,  g_P);

    cudaFuncSetAttribute(gemm_nt<true,  true,  false>,
                         cudaFuncAttributeMaxDynamicSharedMemorySize, SMEM_BYTES);
    cudaFuncSetAttribute(gemm_nt<true,  true,  true>,
                         cudaFuncAttributeMaxDynamicSharedMemorySize, SMEM_BYTES);
    cudaFuncSetAttribute(gemm_nt<false, false, false>,
                         cudaFuncAttributeMaxDynamicSharedMemorySize, SMEM_BYTES);

    dim3 blk(256);
    const long long SD  = (long long)SS * DD;
    const long long SSs = (long long)SS * SS;
    const float scale = 1.0f / sqrtf((float)DD);

    // Q,K projections: [BS, D] x [D, D]^T  (M=16384, N=768, K=768)
    dim3 gq(DD / 128, BS / 128, 1);
    gemm_nt<true, true, false><<<gq, blk, SMEM_BYTES>>>(Z, Wq, bq, Qp, DD, DD, DD, DD, 0, 0, 0, 1.0f);
    gemm_nt<true, true, false><<<gq, blk, SMEM_BYTES>>>(Z, Wk, bk, Kp, DD, DD, DD, DD, 0, 0, 0, 1.0f);

    // Transposed V projection: Vt = Wv @ Z^T  (M=768, N=16384, K=768),
    // bias applied per M-row; output layout Vt[e][b*s], ld = BS.
    dim3 gv(BS / 128, DD / 128, 1);
    gemm_nt<true, true, true ><<<gv, blk, SMEM_BYTES>>>(Wv, Z, bv, Vtp, DD, DD, DD, BS, 0, 0, 0, 1.0f);

    // Scores: per batch, Q @ K^T * scale (operands pre-rounded): M=N=2048, K=768
    dim3 gs(SS / 128, SS / 128, BB);
    gemm_nt<false, false, false><<<gs, blk, SMEM_BYTES>>>(Qp, Kp, nullptr, Pp, DD, DD, DD, SS, SD, SD, SSs, scale);

    // Softmax over each of BS rows (rounds P to tf32 on store)
    softmax_rows<<<BS, blk>>>(Pp);

    // Output: per batch, P @ Vt^T (NT): M=2048, N=768, K=2048
    // B = Vt[e][b*s]: ldb = BS, batch stride = SS.
    dim3 go(DD / 128, SS / 128, BB);
    gemm_nt<false, false, false><<<go, blk, SMEM_BYTES>>>(Pp, Vtp, nullptr, out, SS, SS, BS, DD, SSs, SS, SD, 1.0f);
}

// round 16
// speedup vs baseline: 2.2121x; 1.8736x over previous
#include <cuda_runtime.h>
#include <cuda_fp16.h>
#include <math.h>
#include <stdint.h>

#define BB 8
#define SS 2048
#define DD 768
#define BS (BB * SS)

// Scratch (no cudaMalloc allowed)
__device__ __half g_Zh[BS * DD];               // fp16 Z
__device__ __half g_Wh[3 * DD * DD];           // fp16 Wq,Wk,Wv (contig)
__device__ __half g_Q[BS * DD];
__device__ __half g_K[BS * DD];
__device__ __half g_Vt[BS * DD];               // layout [e][b*s] (ld = BS)
__device__ float  g_S[(long long)BB * SS * SS];  // fp32 logits
__device__ __half g_P[(long long)BB * SS * SS];  // fp16 softmax probs

// 2-stage pipeline, tiles [128 rows][72 halfs] (Kc=64 + 8 pad halfs).
// Bank of (row,halfword h): (36*row + h/2) % 32 -> ldmatrix 8 rows x 16B hits
// banks {4r mod 32} = all distinct. Conflict-free.
#define STAGE_HB (128 * 72 * 2)                // bytes per tile stage
#define SMEM_BYTES (4 * STAGE_HB)              // A0,A1,B0,B1 = 72KB

__device__ __forceinline__ void mma_f16(float c[4],
                                        uint32_t a0, uint32_t a1, uint32_t a2, uint32_t a3,
                                        uint32_t b0, uint32_t b1) {
    asm volatile(
        "mma.sync.aligned.m16n8k16.row.col.f32.f16.f16.f32 "
        "{%0,%1,%2,%3}, {%4,%5,%6,%7}, {%8,%9}, {%0,%1,%2,%3};\n"
        : "+f"(c[0]), "+f"(c[1]), "+f"(c[2]), "+f"(c[3])
        : "r"(a0), "r"(a1), "r"(a2), "r"(a3), "r"(b0), "r"(b1));
}

__device__ __forceinline__ void ldsm4(uint32_t& r0, uint32_t& r1, uint32_t& r2, uint32_t& r3,
                                      uint32_t addr) {
    asm volatile("ldmatrix.sync.aligned.m8n8.x4.shared.b16 {%0,%1,%2,%3}, [%4];\n"
                 : "=r"(r0), "=r"(r1), "=r"(r2), "=r"(r3) : "r"(addr));
}

__device__ __forceinline__ void cpasync16(uint32_t dst, const void* src) {
    asm volatile("cp.async.cg.shared.global [%0], [%1], 16;\n" :: "r"(dst), "l"(src));
}

// ---------------------------------------------------------------------------
// fp16 tensor-core NT GEMM: C = scale*(A @ B^T) + bias   (fp32 accumulate)
//   A:[M,K] ld=lda halfs, B:[N,K] ld=ldb halfs (K-contig), C:[M,N] ld=ldc.
// 128x128 block tile, Kc=64 (4 K=16 slabs per barrier), 2-stage cp.async
// pipeline, 256 threads (8 warps), warp tile 32(M)x64(N) = 2x8 m16n8k16 tiles.
// B-fragments double-buffered across slabs (proven win in R13).
// BROW: bias indexed by M-row (transposed-V projection) else by N-col.
// HOUT: store output as half (else float).
// ---------------------------------------------------------------------------
template <bool BROW, bool HOUT>
__global__ void __launch_bounds__(256, 2)
gemm_h(const __half* __restrict__ A, const __half* __restrict__ Bm,
       const float* __restrict__ bias, void* __restrict__ Cv,
       int K, int lda, int ldb, int ldc,
       long long sA, long long sB, long long sC, float scale)
{
    extern __shared__ __align__(16) char smem[];

    const int b = blockIdx.z;
    A  += (long long)b * sA;
    Bm += (long long)b * sB;
    __half* Ch = HOUT ? ((__half*)Cv + (long long)b * sC) : nullptr;
    float*  Cf = HOUT ? nullptr : ((float*)Cv + (long long)b * sC);

    const int tid   = threadIdx.x;
    const int lane  = tid & 31;
    const int warp  = tid >> 5;
    const int warpM = warp & 3;       // 0..3 -> 32-row slab
    const int warpN = warp >> 2;      // 0..1 -> 64-col slab
    const int grp   = lane >> 2;      // 0..7
    const int qid   = lane & 3;       // 0..3
    const int m0    = blockIdx.y * 128;
    const int n0    = blockIdx.x * 128;

    // ldmatrix per-thread row/matrix assignment
    const int local = lane & 7;
    const int sel   = lane >> 3;      // 0..3
    // A matrices: (row-lo,k-lo),(row-hi,k-lo),(row-lo,k-hi),(row-hi,k-hi)
    const int rowA = warpM * 32 + ((sel & 1) << 3) + local;
    const int kcA  = (sel >> 1) << 3;             // halfs: 0 or 8
    // B matrices: (n-lo,k-lo),(n-lo,k-hi),(n-hi,k-lo),(n-hi,k-hi)
    const int rowB = warpN * 64 + ((sel >> 1) << 3) + local;
    const int kcB  = (sel & 1) << 3;              // halfs: 0 or 8

    const uint32_t as_base = (uint32_t)__cvta_generic_to_shared(smem);
    const uint32_t bs_base = as_base + 2 * STAGE_HB;

    float acc[2][8][4];
#pragma unroll
    for (int mt = 0; mt < 2; mt++)
#pragma unroll
        for (int nt = 0; nt < 8; nt++)
#pragma unroll
            for (int r = 0; r < 4; r++) acc[mt][nt][r] = 0.f;

    // ---- async stage loader: A 128x64h, B 128x64h (128B/row each)
    auto load_stage = [&](int k0, int s) {
#pragma unroll
        for (int i = 0; i < 4; i++) {
            int slot = tid + i * 256;            // 0..1023
            int row  = slot >> 3;                // 0..127
            int j    = slot & 7;                 // 16B chunk = 8 halfs
            cpasync16(as_base + s * STAGE_HB + (row * 72 + j * 8) * 2,
                      &A[(long long)(m0 + row) * lda + k0 + j * 8]);
            cpasync16(bs_base + s * STAGE_HB + (row * 72 + j * 8) * 2,
                      &Bm[(long long)(n0 + row) * ldb + k0 + j * 8]);
        }
        asm volatile("cp.async.commit_group;\n" ::);
    };

    const int NK = K >> 6;            // K / 64
    load_stage(0, 0);

    for (int it = 0; it < NK; it++) {
        if (it + 1 < NK) {
            load_stage((it + 1) << 6, (it + 1) & 1);
            asm volatile("cp.async.wait_group 1;\n" ::);
        } else {
            asm volatile("cp.async.wait_group 0;\n" ::);
        }
        __syncthreads();

        const uint32_t as_s = as_base + (it & 1) * STAGE_HB;
        const uint32_t bs_s = bs_base + (it & 1) * STAGE_HB;

        // B-fragment double buffer: preload slab 0
        uint32_t bf[2][4][4];
#pragma unroll
        for (int p = 0; p < 4; p++) {
            uint32_t addr = bs_s + (((rowB + p * 16) * 72) + kcB) * 2;
            ldsm4(bf[0][p][0], bf[0][p][1], bf[0][p][2], bf[0][p][3], addr);
        }

#pragma unroll
        for (int ks = 0; ks < 4; ks++) {
            const int cur = ks & 1, nxt = cur ^ 1;
            const int kb  = ks * 16;             // halfs

            // A fragments for this slab
            uint32_t af[2][4];
#pragma unroll
            for (int mt = 0; mt < 2; mt++) {
                uint32_t addr = as_s + (((rowA + mt * 16) * 72) + kb + kcA) * 2;
                ldsm4(af[mt][0], af[mt][1], af[mt][2], af[mt][3], addr);
            }
            // Prefetch next slab's B fragments (hidden under this slab's mmas)
            if (ks < 3) {
#pragma unroll
                for (int p = 0; p < 4; p++) {
                    uint32_t addr = bs_s + (((rowB + p * 16) * 72) + kb + 16 + kcB) * 2;
                    ldsm4(bf[nxt][p][0], bf[nxt][p][1], bf[nxt][p][2], bf[nxt][p][3], addr);
                }
            }
            // 16 mmas: p covers n-tiles (2p, 2p+1); bf regs {b0_e, b1_e, b0_o, b1_o}
#pragma unroll
            for (int p = 0; p < 4; p++) {
#pragma unroll
                for (int mt = 0; mt < 2; mt++) {
                    mma_f16(acc[mt][2 * p],     af[mt][0], af[mt][1], af[mt][2], af[mt][3],
                            bf[cur][p][0], bf[cur][p][1]);
                    mma_f16(acc[mt][2 * p + 1], af[mt][0], af[mt][1], af[mt][2], af[mt][3],
                            bf[cur][p][2], bf[cur][p][3]);
                }
            }
        }
        __syncthreads();
    }

    // ---- epilogue: scale + bias, half2 or float2 stores
#pragma unroll
    for (int nt = 0; nt < 8; nt++) {
        int colc = n0 + warpN * 64 + nt * 8 + (qid << 1);
        float bc0 = 0.f, bc1 = 0.f;
        if (bias && !BROW) { bc0 = bias[colc]; bc1 = bias[colc + 1]; }
#pragma unroll
        for (int mt = 0; mt < 2; mt++) {
            int row0 = m0 + warpM * 32 + mt * 16 + grp;
            float br0 = 0.f, br1 = 0.f;
            if (bias && BROW) { br0 = bias[row0]; br1 = bias[row0 + 8]; }
            float v00 = acc[mt][nt][0] * scale + (BROW ? br0 : bc0);
            float v01 = acc[mt][nt][1] * scale + (BROW ? br0 : bc1);
            float v10 = acc[mt][nt][2] * scale + (BROW ? br1 : bc0);
            float v11 = acc[mt][nt][3] * scale + (BROW ? br1 : bc1);
            if (HOUT) {
                *(__half2*)&Ch[(long long)row0 * ldc + colc]       = __floats2half2_rn(v00, v01);
                *(__half2*)&Ch[(long long)(row0 + 8) * ldc + colc] = __floats2half2_rn(v10, v11);
            } else {
                float2 o0; o0.x = v00; o0.y = v01;
                float2 o1; o1.x = v10; o1.y = v11;
                *(float2*)&Cf[(long long)row0 * ldc + colc]       = o0;
                *(float2*)&Cf[(long long)(row0 + 8) * ldc + colc] = o1;
            }
        }
    }
}

// ---------------------------------------------------------------------------
// fp32 -> fp16 conversion, float4-strided
// ---------------------------------------------------------------------------
__global__ void __launch_bounds__(256)
cvt_half_k(const float* __restrict__ in, __half* __restrict__ out, int n4)
{
    int i = blockIdx.x * blockDim.x + threadIdx.x;
    if (i < n4) {
        float4 v = ((const float4*)in)[i];
        ((__half2*)out)[2 * i]     = __floats2half2_rn(v.x, v.y);
        ((__half2*)out)[2 * i + 1] = __floats2half2_rn(v.z, v.w);
    }
}

// ---------------------------------------------------------------------------
// Row softmax: read fp32 logits S, write fp16 probs P. One block per row.
// ---------------------------------------------------------------------------
__global__ void __launch_bounds__(256)
softmax_rows(const float* __restrict__ S, __half* __restrict__ P)
{
    const float* s = S + (long long)blockIdx.x * SS;
    __half*      p = P + (long long)blockIdx.x * SS;
    const int tid  = threadIdx.x;
    const int lane = tid & 31;
    const int wid  = tid >> 5;

    __shared__ float red[8];

    float v[8];
    float mx = -1e30f;
#pragma unroll
    for (int i = 0; i < 8; i++) {
        v[i] = s[tid + i * 256];
        mx = fmaxf(mx, v[i]);
    }
#pragma unroll
    for (int o = 16; o > 0; o >>= 1)
        mx = fmaxf(mx, __shfl_xor_sync(0xffffffffu, mx, o));
    if (lane == 0) red[wid] = mx;
    __syncthreads();
    float rmax = red[0];
#pragma unroll
    for (int i = 1; i < 8; i++) rmax = fmaxf(rmax, red[i]);
    __syncthreads();

    float sum = 0.f;
#pragma unroll
    for (int i = 0; i < 8; i++) {
        v[i] = __expf(v[i] - rmax);
        sum += v[i];
    }
#pragma unroll
    for (int o = 16; o > 0; o >>= 1)
        sum += __shfl_xor_sync(0xffffffffu, sum, o);
    if (lane == 0) red[wid] = sum;
    __syncthreads();
    float tot = 0.f;
#pragma unroll
    for (int i = 0; i < 8; i++) tot += red[i];
    float inv = 1.f / tot;

#pragma unroll
    for (int i = 0; i < 8; i++)
        p[tid + i * 256] = __float2half_rn(v[i] * inv);
}

// ---------------------------------------------------------------------------
// Launch: cvt inputs -> Q,K,Vt projections -> scores(fp32) -> softmax -> PV
// ---------------------------------------------------------------------------
extern "C" void kernel_launch(void* const* d_in, const int* in_sizes, int n_in,
                              void* d_out, int out_size)
{
    const float* Z  = (const float*)d_in[0];
    const float* Wq = (const float*)d_in[1];
    const float* bq = (const float*)d_in[2];
    const float* Wk = (const float*)d_in[3];
    const float* bk = (const float*)d_in[4];
    const float* Wv = (const float*)d_in[5];
    const float* bv = (const float*)d_in[6];
    float* out = (float*)d_out;

    __half *Zh, *Wh, *Qp, *Kp, *Vtp, *Pp;
    float *Sp;
    cudaGetSymbolAddress((void**)&Zh,  g_Zh);
    cudaGetSymbolAddress((void**)&Wh,  g_Wh);
    cudaGetSymbolAddress((void**)&Qp,  g_Q);
    cudaGetSymbolAddress((void**)&Kp,  g_K);
    cudaGetSymbolAddress((void**)&Vtp, g_Vt);
    cudaGetSymbolAddress((void**)&Sp,  g_S);
    cudaGetSymbolAddress((void**)&Pp,  g_P);

    cudaFuncSetAttribute(gemm_h<false, true >,
                         cudaFuncAttributeMaxDynamicSharedMemorySize, SMEM_BYTES);
    cudaFuncSetAttribute(gemm_h<true,  true >,
                         cudaFuncAttributeMaxDynamicSharedMemorySize, SMEM_BYTES);
    cudaFuncSetAttribute(gemm_h<false, false>,
                         cudaFuncAttributeMaxDynamicSharedMemorySize, SMEM_BYTES);

    dim3 blk(256);
    const long long SD  = (long long)SS * DD;
    const long long SSs = (long long)SS * SS;
    const float scale = 1.0f / sqrtf((float)DD);

    // Convert inputs to fp16 (same 11-bit mantissa as tf32; exact rounding point)
    const int nZ4 = (BS * DD) / 4, nW4 = (DD * DD) / 4;
    cvt_half_k<<<(nZ4 + 255) / 256, blk>>>(Z,  Zh, nZ4);
    cvt_half_k<<<(nW4 + 255) / 256, blk>>>(Wq, Wh + 0 * DD * DD, nW4);
    cvt_half_k<<<(nW4 + 255) / 256, blk>>>(Wk, Wh + 1 * DD * DD, nW4);
    cvt_half_k<<<(nW4 + 255) / 256, blk>>>(Wv, Wh + 2 * DD * DD, nW4);

    // Q,K projections: [BS,768] x [768,768]^T, half out
    dim3 gq(DD / 128, BS / 128, 1);
    gemm_h<false, true><<<gq, blk, SMEM_BYTES>>>(Zh, Wh + 0 * DD * DD, bq, Qp,
                                                 DD, DD, DD, DD, 0, 0, 0, 1.0f);
    gemm_h<false, true><<<gq, blk, SMEM_BYTES>>>(Zh, Wh + 1 * DD * DD, bk, Kp,
                                                 DD, DD, DD, DD, 0, 0, 0, 1.0f);

    // Transposed V projection: Vt = Wv @ Z^T (M=768, N=BS), bias per M-row, half out
    dim3 gv(BS / 128, DD / 128, 1);
    gemm_h<true, true><<<gv, blk, SMEM_BYTES>>>(Wh + 2 * DD * DD, Zh, bv, Vtp,
                                                DD, DD, DD, BS, 0, 0, 0, 1.0f);

    // Scores: per batch, Q @ K^T * scale -> fp32 logits (no extra rounding)
    dim3 gs(SS / 128, SS / 128, BB);
    gemm_h<false, false><<<gs, blk, SMEM_BYTES>>>(Qp, Kp, nullptr, Sp,
                                                  DD, DD, DD, SS, SD, SD, SSs, scale);

    // Softmax: fp32 logits -> fp16 probs
    softmax_rows<<<BS, blk>>>(Sp, Pp);

    // Output: per batch, P @ Vt^T (M=2048, N=768, K=2048), fp32 out
    dim3 go(DD / 128, SS / 128, BB);
    gemm_h<false, false><<<go, blk, SMEM_BYTES>>>(Pp, Vtp, nullptr, out,
                                                  SS, SS, BS, DD, SSs, SS, SD, 1.0f);
}